// round 2
// baseline (speedup 1.0000x reference)
#include <cuda_runtime.h>
#include <cstdint>
#include <cstddef>

// Problem constants (fixed shapes per reference)
#define BB 4
#define LL 4096
#define DD 1024
#define MM (BB * LL)      // 16384
#define KK DD             // 1024
#define SEG 64            // segments along L
#define SL  (LL / SEG)    // 64 steps per segment

// GEMM tiling
#define BM 64
#define BN 64
#define BK 16
#define SSTR (BK + 4)     // smem row stride (floats) -> 20, keeps float4 alignment

// Scratch (allocation-free rule: __device__ globals)
__device__ float g_at[(size_t)MM * DD];     // a_t  [B,L,D]
__device__ float g_bt[(size_t)MM * DD];     // b_t  [B,L,D]
__device__ float g_P [BB * SEG * DD];       // per-segment prod(a)
__device__ float g_H [BB * SEG * DD];       // per-segment local final h
__device__ float g_hin[BB * SEG * DD];      // per-segment incoming h

__device__ __forceinline__ unsigned f2tf(float f) {
    unsigned r;
    asm("cvt.rna.tf32.f32 %0, %1;" : "=r"(r) : "f"(f));
    return r;
}

__device__ __forceinline__ void mma_tf32(float c[4], const unsigned a[4], const unsigned b[2]) {
    asm volatile(
        "mma.sync.aligned.m16n8k8.row.col.f32.tf32.tf32.f32 "
        "{%0,%1,%2,%3}, {%4,%5,%6,%7}, {%8,%9}, {%0,%1,%2,%3};"
        : "+f"(c[0]), "+f"(c[1]), "+f"(c[2]), "+f"(c[3])
        : "r"(a[0]), "r"(a[1]), "r"(a[2]), "r"(a[3]), "r"(b[0]), "r"(b[1]));
}

// Fused dual GEMM: z_a = x @ Wa^T, z_x = x @ Wx^T, epilogue -> a_t, b_t
__global__ __launch_bounds__(128) void gemm_gates(
    const float* __restrict__ x, const float* __restrict__ Wa,
    const float* __restrict__ Wx, const float* __restrict__ ba,
    const float* __restrict__ bx, const float* __restrict__ lmbd)
{
    __shared__ unsigned sA [BM * SSTR];
    __shared__ unsigned sWa[BN * SSTR];
    __shared__ unsigned sWx[BN * SSTR];

    const int tid  = threadIdx.x;
    const int warp = tid >> 5, lane = tid & 31;
    const int g = lane >> 2, tg = lane & 3;
    const int wm = (warp >> 1) * 32;   // warp tile offset in M (2x2 warps)
    const int wn = (warp & 1) * 32;    // warp tile offset in N

    const int m0 = blockIdx.y * BM;
    const int n0 = blockIdx.x * BN;

    float accA[2][4][4];
    float accX[2][4][4];
    #pragma unroll
    for (int i = 0; i < 2; i++)
        #pragma unroll
        for (int j = 0; j < 4; j++)
            #pragma unroll
            for (int k = 0; k < 4; k++) { accA[i][j][k] = 0.f; accX[i][j][k] = 0.f; }

    for (int k0 = 0; k0 < KK; k0 += BK) {
        // Load A tile (64x16) and both W tiles (64x16 each). 256 float4 per tile.
        #pragma unroll
        for (int i = 0; i < 2; i++) {
            int idx = tid + i * 128;
            int r = idx >> 2, c4 = (idx & 3) * 4;
            float4 v = *(const float4*)(x + (size_t)(m0 + r) * KK + k0 + c4);
            unsigned* dst = &sA[r * SSTR + c4];
            dst[0] = f2tf(v.x); dst[1] = f2tf(v.y); dst[2] = f2tf(v.z); dst[3] = f2tf(v.w);
        }
        #pragma unroll
        for (int i = 0; i < 2; i++) {
            int idx = tid + i * 128;
            int r = idx >> 2, c4 = (idx & 3) * 4;
            {
                float4 v = *(const float4*)(Wa + (size_t)(n0 + r) * KK + k0 + c4);
                unsigned* dst = &sWa[r * SSTR + c4];
                dst[0] = f2tf(v.x); dst[1] = f2tf(v.y); dst[2] = f2tf(v.z); dst[3] = f2tf(v.w);
            }
            {
                float4 v = *(const float4*)(Wx + (size_t)(n0 + r) * KK + k0 + c4);
                unsigned* dst = &sWx[r * SSTR + c4];
                dst[0] = f2tf(v.x); dst[1] = f2tf(v.y); dst[2] = f2tf(v.z); dst[3] = f2tf(v.w);
            }
        }
        __syncthreads();

        #pragma unroll
        for (int kk = 0; kk < BK; kk += 8) {
            unsigned af[2][4];
            #pragma unroll
            for (int mt = 0; mt < 2; mt++) {
                int rb = wm + mt * 16;
                af[mt][0] = sA[(rb + g    ) * SSTR + kk + tg    ];
                af[mt][1] = sA[(rb + g + 8) * SSTR + kk + tg    ];
                af[mt][2] = sA[(rb + g    ) * SSTR + kk + tg + 4];
                af[mt][3] = sA[(rb + g + 8) * SSTR + kk + tg + 4];
            }
            #pragma unroll
            for (int nt = 0; nt < 4; nt++) {
                int nb = wn + nt * 8;
                unsigned bfA[2], bfX[2];
                bfA[0] = sWa[(nb + g) * SSTR + kk + tg    ];
                bfA[1] = sWa[(nb + g) * SSTR + kk + tg + 4];
                bfX[0] = sWx[(nb + g) * SSTR + kk + tg    ];
                bfX[1] = sWx[(nb + g) * SSTR + kk + tg + 4];
                #pragma unroll
                for (int mt = 0; mt < 2; mt++) {
                    mma_tf32(accA[mt][nt], af[mt], bfA);
                    mma_tf32(accX[mt][nt], af[mt], bfX);
                }
            }
        }
        __syncthreads();
    }

    // Epilogue: gates -> a_t, b_t
    #pragma unroll
    for (int mt = 0; mt < 2; mt++) {
        #pragma unroll
        for (int nt = 0; nt < 4; nt++) {
            const float* cA = accA[mt][nt];
            const float* cX = accX[mt][nt];
            #pragma unroll
            for (int cc = 0; cc < 2; cc++) {
                int n = n0 + wn + nt * 8 + 2 * tg + cc;
                float ban = ba[n], bxn = bx[n];
                float la = -log1pf(expf(-lmbd[n]));   // log(sigmoid(lmbd))
                #pragma unroll
                for (int half = 0; half < 2; half++) {
                    int m = m0 + wm + mt * 16 + g + half * 8;
                    float za = cA[half * 2 + cc] + ban;
                    float zx = cX[half * 2 + cc] + bxn;
                    float r  = 1.f / (1.f + expf(-za));
                    float ig = 1.f / (1.f + expf(-zx));
                    float at = expf(8.f * r * la);
                    float xv = x[(size_t)m * DD + n];
                    float bt = sqrtf(fmaxf(0.f, 1.f - at * at)) * ig * xv;
                    size_t o = (size_t)m * DD + n;
                    g_at[o] = at;
                    g_bt[o] = bt;
                }
            }
        }
    }
}

// Pass 1: per-segment local scan -> (P = prod a, H = local final h)
__global__ __launch_bounds__(256) void scan_pass1()
{
    int gidx = blockIdx.x * 256 + threadIdx.x;       // [0, BB*SEG*DD)
    int d    = gidx & (DD - 1);
    int sidx = gidx >> 10;                           // / DD
    int b    = sidx >> 6;                            // / SEG
    int s    = sidx & (SEG - 1);
    size_t base = ((size_t)(b * LL + s * SL)) * DD + d;
    float h = 0.f, P = 1.f;
    #pragma unroll 8
    for (int t = 0; t < SL; t++) {
        float a  = g_at[base + (size_t)t * DD];
        float bt = g_bt[base + (size_t)t * DD];
        h = fmaf(a, h, bt);
        P *= a;
    }
    g_P[sidx * DD + d] = P;
    g_H[sidx * DD + d] = h;
}

// Pass 2: scan segment carries per (b, d) chain
__global__ __launch_bounds__(256) void scan_pass2()
{
    int gidx = blockIdx.x * 256 + threadIdx.x;       // [0, BB*DD)
    int d = gidx & (DD - 1);
    int b = gidx >> 10;
    float carry = 0.f;
    #pragma unroll 8
    for (int s = 0; s < SEG; s++) {
        int w = (b * SEG + s) * DD + d;
        g_hin[w] = carry;
        carry = fmaf(g_P[w], carry, g_H[w]);
    }
}

// Pass 3: re-run each segment with incoming h, write output
__global__ __launch_bounds__(256) void scan_pass3(float* __restrict__ out)
{
    int gidx = blockIdx.x * 256 + threadIdx.x;
    int d    = gidx & (DD - 1);
    int sidx = gidx >> 10;
    int b    = sidx >> 6;
    int s    = sidx & (SEG - 1);
    size_t base = ((size_t)(b * LL + s * SL)) * DD + d;
    float h = g_hin[sidx * DD + d];
    #pragma unroll 8
    for (int t = 0; t < SL; t++) {
        size_t idx = base + (size_t)t * DD;
        h = fmaf(g_at[idx], h, g_bt[idx]);
        out[idx] = h;
    }
}

extern "C" void kernel_launch(void* const* d_in, const int* in_sizes, int n_in,
                              void* d_out, int out_size)
{
    (void)in_sizes; (void)n_in; (void)out_size;
    const float* x    = (const float*)d_in[0];
    const float* Wa   = (const float*)d_in[1];
    const float* Wx   = (const float*)d_in[2];
    const float* ba   = (const float*)d_in[3];
    const float* bx   = (const float*)d_in[4];
    const float* lmbd = (const float*)d_in[5];
    float* out = (float*)d_out;

    dim3 grid(DD / BN, MM / BM);   // 16 x 256
    gemm_gates<<<grid, 128>>>(x, Wa, Wx, ba, bx, lmbd);
    scan_pass1<<<(BB * SEG * DD) / 256, 256>>>();
    scan_pass2<<<(BB * DD) / 256, 256>>>();
    scan_pass3<<<(BB * SEG * DD) / 256, 256>>>(out);
}

// round 5
// speedup vs baseline: 1.1097x; 1.1097x over previous
#include <cuda_runtime.h>
#include <cstdint>
#include <cstddef>

// Problem constants
#define BB 4
#define LL 4096
#define DD 1024
#define MM (BB * LL)      // 16384
#define KK 1024
#define SEG 64
#define SL  64

// GEMM tiling (mma.sync tf32 path — tcgen05 PTX is rejected by this harness's
// non-'a' PTX target, so we optimize the legacy tensor path instead)
#define BM 128            // CTA M tile
#define BN 128            // CTA N tile PER GATE (two gates share the A tile)
#define BK 32             // k-chunk (one 128B row)
#define NKC (KK / BK)     // 32
#define SSTR 36           // smem row stride in floats (32 + 4 pad, 16B-aligned)
#define PIPE 3

#define STAGE_ARR_BYTES (128 * SSTR * 4)          // 18432 per array
#define STAGE_BYTES (3 * STAGE_ARR_BYTES)         // A + Wa + Wx = 55296
#define SM_BIAS  64                                // 3 * 128 floats
#define SM_STAGE 4096
#define SMEM_TOTAL (SM_STAGE + PIPE * STAGE_BYTES) // 169984 B

// Scratch (allocation-free rule: __device__ globals)
__device__ float g_at[(size_t)MM * DD];
__device__ float g_bt[(size_t)MM * DD];
__device__ float g_P [BB * SEG * DD];
__device__ float g_H [BB * SEG * DD];
__device__ float g_hin[BB * SEG * DD];

// ---------- helpers ----------
__device__ __forceinline__ uint32_t smem_u32(const void* p) {
    uint32_t a;
    asm("{ .reg .u64 t; cvta.to.shared.u64 t, %1; cvt.u32.u64 %0, t; }" : "=r"(a) : "l"(p));
    return a;
}

__device__ __forceinline__ void cpa16(uint32_t dst, const void* src) {
    asm volatile("cp.async.cg.shared.global [%0], [%1], 16;" :: "r"(dst), "l"(src));
}

__device__ __forceinline__ unsigned f2tf(float f) {
    unsigned r;
    asm("cvt.rna.tf32.f32 %0, %1;" : "=r"(r) : "f"(f));
    return r;
}

__device__ __forceinline__ void mma_tf32(float c[4], const unsigned a[4], const unsigned b[2]) {
    asm volatile(
        "mma.sync.aligned.m16n8k8.row.col.f32.tf32.tf32.f32 "
        "{%0,%1,%2,%3}, {%4,%5,%6,%7}, {%8,%9}, {%0,%1,%2,%3};"
        : "+f"(c[0]), "+f"(c[1]), "+f"(c[2]), "+f"(c[3])
        : "r"(a[0]), "r"(a[1]), "r"(a[2]), "r"(a[3]), "r"(b[0]), "r"(b[1]));
}

// ---------- fused dual GEMM + gate epilogue ----------
__global__ __launch_bounds__(256, 1)
void gemm_gates(const float* __restrict__ x, const float* __restrict__ Wa,
                const float* __restrict__ Wx, const float* __restrict__ ba,
                const float* __restrict__ bx, const float* __restrict__ lmbd)
{
    extern __shared__ char sm[];
    const uint32_t sb = smem_u32(sm);
    const int tid  = threadIdx.x;
    const int wid  = tid >> 5, lane = tid & 31;
    const int g = lane >> 2, tg = lane & 3;
    const int wm2 = wid >> 2;          // 0..1 -> M offset 64
    const int wn4 = wid & 3;           // 0..3 -> N offset 32
    const int m0 = blockIdx.y * BM;
    const int n0 = blockIdx.x * BN;

    float* s_ba = (float*)(sm + SM_BIAS);
    float* s_bx = s_ba + BN;
    float* s_la = s_bx + BN;
    for (int i = tid; i < BN; i += 256) {
        s_ba[i] = ba[n0 + i];
        s_bx[i] = bx[n0 + i];
        s_la[i] = -log1pf(expf(-lmbd[n0 + i]));   // log(sigmoid(lmbd))
    }

    const float* xb  = x  + (size_t)m0 * KK;
    const float* wab = Wa + (size_t)n0 * KK;
    const float* wxb = Wx + (size_t)n0 * KK;

    // stage loader: A 128x32, Wa 128x32, Wx 128x32 (raw fp32, cp.async 16B)
    auto load_stage = [&](int s, int kc) {
        const uint32_t bA  = sb + SM_STAGE + s * STAGE_BYTES;
        const uint32_t bWa = bA + STAGE_ARR_BYTES;
        const uint32_t bWx = bWa + STAGE_ARR_BYTES;
        const int ko = kc * BK;
        #pragma unroll
        for (int i = 0; i < 4; i++) {              // 1024 segs per array / 256 thr
            int seg = tid + i * 256;
            int r = seg >> 3, c = seg & 7;
            uint32_t so = (uint32_t)(r * (SSTR * 4) + c * 16);
            size_t  go = (size_t)r * KK + ko + c * 4;
            cpa16(bA  + so, xb  + go);
            cpa16(bWa + so, wab + go);
            cpa16(bWx + so, wxb + go);
        }
    };

    float accA[4][4][4];   // [mt][nt][4]
    float accX[4][4][4];
    #pragma unroll
    for (int a = 0; a < 4; a++)
        #pragma unroll
        for (int b = 0; b < 4; b++)
            #pragma unroll
            for (int c = 0; c < 4; c++) { accA[a][b][c] = 0.f; accX[a][b][c] = 0.f; }

    load_stage(0, 0);
    asm volatile("cp.async.commit_group;" ::: "memory");
    load_stage(1, 1);
    asm volatile("cp.async.commit_group;" ::: "memory");

    for (int kc = 0; kc < NKC; kc++) {
        if (kc + 2 < NKC) load_stage((kc + 2) % PIPE, kc + 2);
        asm volatile("cp.async.commit_group;" ::: "memory");   // may be empty
        asm volatile("cp.async.wait_group 2;" ::: "memory");   // stage kc ready
        __syncthreads();

        const float* sAp  = (const float*)(sm + SM_STAGE + (kc % PIPE) * STAGE_BYTES);
        const float* sWap = sAp  + 128 * SSTR;
        const float* sWxp = sWap + 128 * SSTR;

        #pragma unroll
        for (int kk = 0; kk < BK; kk += 8) {
            unsigned af[4][4];
            #pragma unroll
            for (int mt = 0; mt < 4; mt++) {
                int rb = wm2 * 64 + mt * 16;
                af[mt][0] = f2tf(sAp[(rb + g    ) * SSTR + kk + tg    ]);
                af[mt][1] = f2tf(sAp[(rb + g + 8) * SSTR + kk + tg    ]);
                af[mt][2] = f2tf(sAp[(rb + g    ) * SSTR + kk + tg + 4]);
                af[mt][3] = f2tf(sAp[(rb + g + 8) * SSTR + kk + tg + 4]);
            }
            unsigned bfa[4][2], bfx[4][2];
            #pragma unroll
            for (int nt = 0; nt < 4; nt++) {
                int nb = wn4 * 32 + nt * 8;
                bfa[nt][0] = f2tf(sWap[(nb + g) * SSTR + kk + tg    ]);
                bfa[nt][1] = f2tf(sWap[(nb + g) * SSTR + kk + tg + 4]);
                bfx[nt][0] = f2tf(sWxp[(nb + g) * SSTR + kk + tg    ]);
                bfx[nt][1] = f2tf(sWxp[(nb + g) * SSTR + kk + tg + 4]);
            }
            #pragma unroll
            for (int mt = 0; mt < 4; mt++)
                #pragma unroll
                for (int nt = 0; nt < 4; nt++) {
                    mma_tf32(accA[mt][nt], af[mt], bfa[nt]);
                    mma_tf32(accX[mt][nt], af[mt], bfx[nt]);
                }
        }
        __syncthreads();   // protect stage buffer before next prefetch overwrites it
    }

    // Epilogue: re-stage each warp's 64x32-per-gate tile through SMEM (stride 33)
    // so global stores are fully coalesced.
    float* epi  = (float*)(sm + SM_STAGE) + wid * 4224;   // 2 gates * 64*33 floats
    float* epiX = epi + 2112;
    #pragma unroll
    for (int mt = 0; mt < 4; mt++) {
        #pragma unroll
        for (int nt = 0; nt < 4; nt++) {
            int r0 = mt * 16 + g, c0 = nt * 8 + 2 * tg;
            epi [ r0      * 33 + c0    ] = accA[mt][nt][0];
            epi [ r0      * 33 + c0 + 1] = accA[mt][nt][1];
            epi [(r0 + 8) * 33 + c0    ] = accA[mt][nt][2];
            epi [(r0 + 8) * 33 + c0 + 1] = accA[mt][nt][3];
            epiX[ r0      * 33 + c0    ] = accX[mt][nt][0];
            epiX[ r0      * 33 + c0 + 1] = accX[mt][nt][1];
            epiX[(r0 + 8) * 33 + c0    ] = accX[mt][nt][2];
            epiX[(r0 + 8) * 33 + c0 + 1] = accX[mt][nt][3];
        }
    }
    __syncwarp();

    const int nl = wn4 * 32 + lane;
    const int n  = n0 + nl;
    const float ban = s_ba[nl], bxn = s_bx[nl], la = s_la[nl];
    #pragma unroll 4
    for (int r = 0; r < 64; r++) {
        float za = epi [r * 33 + lane] + ban;
        float zx = epiX[r * 33 + lane] + bxn;
        float rr = 1.f / (1.f + expf(-za));
        float ii = 1.f / (1.f + expf(-zx));
        float at = expf(8.f * rr * la);
        int m = m0 + wm2 * 64 + r;
        float xv = x[(size_t)m * KK + n];
        float bt = sqrtf(fmaxf(0.f, 1.f - at * at)) * ii * xv;
        size_t o = (size_t)m * DD + n;
        g_at[o] = at;
        g_bt[o] = bt;
    }
}

// ---------- scan passes (near HBM roofline already) ----------
__global__ __launch_bounds__(256) void scan_pass1()
{
    int gidx = blockIdx.x * 256 + threadIdx.x;
    int d    = gidx & (DD - 1);
    int sidx = gidx >> 10;
    int b    = sidx >> 6;
    int s    = sidx & (SEG - 1);
    size_t base = ((size_t)(b * LL + s * SL)) * DD + d;
    float h = 0.f, P = 1.f;
    #pragma unroll 8
    for (int t = 0; t < SL; t++) {
        float a  = g_at[base + (size_t)t * DD];
        float bt = g_bt[base + (size_t)t * DD];
        h = fmaf(a, h, bt);
        P *= a;
    }
    g_P[sidx * DD + d] = P;
    g_H[sidx * DD + d] = h;
}

__global__ __launch_bounds__(256) void scan_pass2()
{
    int gidx = blockIdx.x * 256 + threadIdx.x;
    int d = gidx & (DD - 1);
    int b = gidx >> 10;
    float carry = 0.f;
    #pragma unroll 8
    for (int s = 0; s < SEG; s++) {
        int w = (b * SEG + s) * DD + d;
        g_hin[w] = carry;
        carry = fmaf(g_P[w], carry, g_H[w]);
    }
}

__global__ __launch_bounds__(256) void scan_pass3(float* __restrict__ out)
{
    int gidx = blockIdx.x * 256 + threadIdx.x;
    int d    = gidx & (DD - 1);
    int sidx = gidx >> 10;
    int b    = sidx >> 6;
    int s    = sidx & (SEG - 1);
    size_t base = ((size_t)(b * LL + s * SL)) * DD + d;
    float h = g_hin[sidx * DD + d];
    #pragma unroll 8
    for (int t = 0; t < SL; t++) {
        size_t idx = base + (size_t)t * DD;
        h = fmaf(g_at[idx], h, g_bt[idx]);
        out[idx] = h;
    }
}

extern "C" void kernel_launch(void* const* d_in, const int* in_sizes, int n_in,
                              void* d_out, int out_size)
{
    (void)in_sizes; (void)n_in; (void)out_size;
    const float* x    = (const float*)d_in[0];
    const float* Wa   = (const float*)d_in[1];
    const float* Wx   = (const float*)d_in[2];
    const float* ba   = (const float*)d_in[3];
    const float* bx   = (const float*)d_in[4];
    const float* lmbd = (const float*)d_in[5];
    float* out = (float*)d_out;

    static int smem_set = 0;
    if (!smem_set) {
        cudaFuncSetAttribute(gemm_gates, cudaFuncAttributeMaxDynamicSharedMemorySize, SMEM_TOTAL);
        smem_set = 1;
    }

    dim3 grid(DD / BN, MM / BM);   // 8 x 128 = 1024 CTAs
    gemm_gates<<<grid, 256, SMEM_TOTAL>>>(x, Wa, Wx, ba, bx, lmbd);
    scan_pass1<<<(BB * SEG * DD) / 256, 256>>>();
    scan_pass2<<<(BB * DD) / 256, 256>>>();
    scan_pass3<<<(BB * SEG * DD) / 256, 256>>>(out);
}

// round 7
// speedup vs baseline: 1.3765x; 1.2405x over previous
#include <cuda_runtime.h>
#include <cuda_fp16.h>
#include <cstdint>
#include <cstddef>

// Problem constants
#define BB 4
#define LL 4096
#define DD 1024
#define MM (BB * LL)      // 16384
#define KK 1024
#define SEG 64
#define SL  64

// GEMM tiling (fp16 mma.sync m16n8k16)
#define BM 128
#define BN 128
#define BK 64             // k-chunk in halves = 128B per row
#define NKC (KK / BK)     // 16
#define PIPE 3

#define ARR_BYTES 16384                    // 128 rows x 128B
#define STAGE_BYTES (3 * ARR_BYTES)        // 49152
#define SM_BIAS  64
#define SM_STAGE 4096
#define SMEM_TOTAL (SM_STAGE + PIPE * STAGE_BYTES)  // 151552 B

#define SWZ(o) ((o) ^ (((o) >> 3) & 0x70))

// Scratch (allocation-free rule: __device__ globals)
__device__ float  g_at[(size_t)MM * DD];
__device__ float  g_bt[(size_t)MM * DD];
__device__ float  g_P [BB * SEG * DD];
__device__ float  g_H [BB * SEG * DD];
__device__ float  g_hin[BB * SEG * DD];
__device__ __half g_x16 [(size_t)MM * KK];
__device__ __half g_wa16[(size_t)DD * KK];
__device__ __half g_wx16[(size_t)DD * KK];

// ---------- helpers ----------
__device__ __forceinline__ uint32_t smem_u32(const void* p) {
    uint32_t a;
    asm("{ .reg .u64 t; cvta.to.shared.u64 t, %1; cvt.u32.u64 %0, t; }" : "=r"(a) : "l"(p));
    return a;
}

__device__ __forceinline__ void cpa16(uint32_t dst, const void* src) {
    asm volatile("cp.async.cg.shared.global [%0], [%1], 16;" :: "r"(dst), "l"(src));
}

__device__ __forceinline__ void ldmx4(uint32_t r[4], uint32_t addr) {
    asm volatile("ldmatrix.sync.aligned.m8n8.x4.shared.b16 {%0,%1,%2,%3}, [%4];"
                 : "=r"(r[0]), "=r"(r[1]), "=r"(r[2]), "=r"(r[3]) : "r"(addr));
}

__device__ __forceinline__ void mma_f16(float c[4], const uint32_t a[4], const uint32_t b[2]) {
    asm volatile(
        "mma.sync.aligned.m16n8k16.row.col.f32.f16.f16.f32 "
        "{%0,%1,%2,%3}, {%4,%5,%6,%7}, {%8,%9}, {%0,%1,%2,%3};"
        : "+f"(c[0]), "+f"(c[1]), "+f"(c[2]), "+f"(c[3])
        : "r"(a[0]), "r"(a[1]), "r"(a[2]), "r"(a[3]), "r"(b[0]), "r"(b[1]));
}

// ---------- fp32 -> fp16 pre-convert ----------
__global__ __launch_bounds__(256) void convert_f16(
    const float* __restrict__ x, const float* __restrict__ Wa, const float* __restrict__ Wx)
{
    size_t gid = (size_t)blockIdx.x * 256 + threadIdx.x;   // 4M threads, 4 elems each
    {
        float4 v = *(const float4*)(x + gid * 4);
        __half2* d = (__half2*)g_x16 + gid * 2;
        d[0] = __floats2half2_rn(v.x, v.y);
        d[1] = __floats2half2_rn(v.z, v.w);
    }
    if (gid < (size_t)(DD * KK) / 4) {
        float4 va = *(const float4*)(Wa + gid * 4);
        float4 vx = *(const float4*)(Wx + gid * 4);
        __half2* da = (__half2*)g_wa16 + gid * 2;
        __half2* dx = (__half2*)g_wx16 + gid * 2;
        da[0] = __floats2half2_rn(va.x, va.y);
        da[1] = __floats2half2_rn(va.z, va.w);
        dx[0] = __floats2half2_rn(vx.x, vx.y);
        dx[1] = __floats2half2_rn(vx.z, vx.w);
    }
}

// ---------- fused dual GEMM + gates + per-segment scan (pass1 fused) ----------
__global__ __launch_bounds__(256, 1)
void gemm_gates(const float* __restrict__ x, const float* __restrict__ ba,
                const float* __restrict__ bx, const float* __restrict__ lmbd)
{
    extern __shared__ char sm[];
    const uint32_t sb = smem_u32(sm);
    const int tid  = threadIdx.x;
    const int wid  = tid >> 5, lane = tid & 31;
    const int g = lane >> 2, tg = lane & 3;
    const int wm2 = wid >> 2;
    const int wn4 = wid & 3;
    const int m0 = blockIdx.y * BM;
    const int n0 = blockIdx.x * BN;

    float* s_ba = (float*)(sm + SM_BIAS);
    float* s_bx = s_ba + BN;
    float* s_la = s_bx + BN;
    for (int i = tid; i < BN; i += 256) {
        s_ba[i] = ba[n0 + i];
        s_bx[i] = bx[n0 + i];
        s_la[i] = -log1pf(expf(-lmbd[n0 + i]));   // log(sigmoid(lmbd))
    }

    const __half* xb  = g_x16  + (size_t)m0 * KK;
    const __half* wab = g_wa16 + (size_t)n0 * KK;
    const __half* wxb = g_wx16 + (size_t)n0 * KK;

    auto load_stage = [&](int s, int kc) {
        const uint32_t bA = sb + SM_STAGE + s * STAGE_BYTES;
        const int ko = kc * BK;
        #pragma unroll
        for (int i = 0; i < 4; i++) {
            int seg = tid + i * 256;
            int r = seg >> 3, c = seg & 7;
            uint32_t so = SWZ((uint32_t)(r * 128 + c * 16));
            size_t  go = (size_t)r * KK + ko + c * 8;
            cpa16(bA                 + so, xb  + go);
            cpa16(bA + ARR_BYTES     + so, wab + go);
            cpa16(bA + 2 * ARR_BYTES + so, wxb + go);
        }
    };

    float accA[4][4][4];
    float accX[4][4][4];
    #pragma unroll
    for (int a = 0; a < 4; a++)
        #pragma unroll
        for (int b = 0; b < 4; b++)
            #pragma unroll
            for (int c = 0; c < 4; c++) { accA[a][b][c] = 0.f; accX[a][b][c] = 0.f; }

    load_stage(0, 0);
    asm volatile("cp.async.commit_group;" ::: "memory");
    load_stage(1, 1);
    asm volatile("cp.async.commit_group;" ::: "memory");

    const int rowA_l = (lane & 15);
    const int segA_l = ((lane >> 4) & 1) * 16;
    const int rowB_l = ((lane >> 4) << 3) + (lane & 7);
    const int segB_l = ((lane >> 3) & 1) * 16;

    for (int kc = 0; kc < NKC; kc++) {
        if (kc + 2 < NKC) load_stage((kc + 2) % PIPE, kc + 2);
        asm volatile("cp.async.commit_group;" ::: "memory");
        asm volatile("cp.async.wait_group 2;" ::: "memory");
        __syncthreads();

        const uint32_t bA  = sb + SM_STAGE + (kc % PIPE) * STAGE_BYTES;
        const uint32_t bWa = bA + ARR_BYTES;
        const uint32_t bWx = bA + 2 * ARR_BYTES;

        #pragma unroll
        for (int kk = 0; kk < 4; kk++) {
            const int kb = kk * 32;
            uint32_t af[4][4];
            #pragma unroll
            for (int mt = 0; mt < 4; mt++) {
                int row = wm2 * 64 + mt * 16 + rowA_l;
                ldmx4(af[mt], bA + SWZ((uint32_t)(row * 128 + kb + segA_l)));
            }
            uint32_t bfa[4][2], bfx[4][2];
            #pragma unroll
            for (int p = 0; p < 2; p++) {
                int row = wn4 * 32 + p * 16 + rowB_l;
                uint32_t so = SWZ((uint32_t)(row * 128 + kb + segB_l));
                uint32_t t[4];
                ldmx4(t, bWa + so);
                bfa[2*p][0] = t[0]; bfa[2*p][1] = t[1];
                bfa[2*p+1][0] = t[2]; bfa[2*p+1][1] = t[3];
                ldmx4(t, bWx + so);
                bfx[2*p][0] = t[0]; bfx[2*p][1] = t[1];
                bfx[2*p+1][0] = t[2]; bfx[2*p+1][1] = t[3];
            }
            #pragma unroll
            for (int mt = 0; mt < 4; mt++)
                #pragma unroll
                for (int nt = 0; nt < 4; nt++) {
                    mma_f16(accA[mt][nt], af[mt], bfa[nt]);
                    mma_f16(accX[mt][nt], af[mt], bfx[nt]);
                }
        }
        __syncthreads();
    }

    // Epilogue: SMEM transpose re-stage + gates + fused per-segment scan
    float* epi  = (float*)(sm + SM_STAGE) + wid * 4224;
    float* epiX = epi + 2112;
    #pragma unroll
    for (int mt = 0; mt < 4; mt++) {
        #pragma unroll
        for (int nt = 0; nt < 4; nt++) {
            int r0 = mt * 16 + g, c0 = nt * 8 + 2 * tg;
            epi [ r0      * 33 + c0    ] = accA[mt][nt][0];
            epi [ r0      * 33 + c0 + 1] = accA[mt][nt][1];
            epi [(r0 + 8) * 33 + c0    ] = accA[mt][nt][2];
            epi [(r0 + 8) * 33 + c0 + 1] = accA[mt][nt][3];
            epiX[ r0      * 33 + c0    ] = accX[mt][nt][0];
            epiX[ r0      * 33 + c0 + 1] = accX[mt][nt][1];
            epiX[(r0 + 8) * 33 + c0    ] = accX[mt][nt][2];
            epiX[(r0 + 8) * 33 + c0 + 1] = accX[mt][nt][3];
        }
    }
    __syncwarp();

    const int nl = wn4 * 32 + lane;
    const int n  = n0 + nl;
    const float ban = s_ba[nl], bxn = s_bx[nl], la = s_la[nl];
    float hseg = 0.f, Pseg = 1.f;
    #pragma unroll 4
    for (int r = 0; r < 64; r++) {
        float za = epi [r * 33 + lane] + ban;
        float zx = epiX[r * 33 + lane] + bxn;
        float rr = 1.f / (1.f + expf(-za));
        float ii = 1.f / (1.f + expf(-zx));
        float at = expf(8.f * rr * la);
        int m = m0 + wm2 * 64 + r;
        float xv = x[(size_t)m * KK + n];
        float bt = sqrtf(fmaxf(0.f, 1.f - at * at)) * ii * xv;
        size_t o = (size_t)m * DD + n;
        g_at[o] = at;
        g_bt[o] = bt;
        hseg = fmaf(at, hseg, bt);
        Pseg *= at;
    }
    {
        int b  = m0 >> 12;
        int s  = ((m0 & 4095) + wm2 * 64) >> 6;
        int w  = (b * SEG + s) * DD + n;
        g_P[w] = Pseg;
        g_H[w] = hseg;
    }
}

// ---------- scan passes ----------
__global__ __launch_bounds__(256) void scan_pass2()
{
    int gidx = blockIdx.x * 256 + threadIdx.x;
    int d = gidx & (DD - 1);
    int b = gidx >> 10;
    float carry = 0.f;
    #pragma unroll 8
    for (int s = 0; s < SEG; s++) {
        int w = (b * SEG + s) * DD + d;
        g_hin[w] = carry;
        carry = fmaf(g_P[w], carry, g_H[w]);
    }
}

__global__ __launch_bounds__(256) void scan_pass3(float* __restrict__ out)
{
    int gidx = blockIdx.x * 256 + threadIdx.x;
    int d    = gidx & (DD - 1);
    int sidx = gidx >> 10;
    int b    = sidx >> 6;
    int s    = sidx & (SEG - 1);
    size_t base = ((size_t)(b * LL + s * SL)) * DD + d;
    float h = g_hin[sidx * DD + d];
    #pragma unroll 8
    for (int t = 0; t < SL; t++) {
        size_t idx = base + (size_t)t * DD;
        h = fmaf(g_at[idx], h, g_bt[idx]);
        out[idx] = h;
    }
}

extern "C" void kernel_launch(void* const* d_in, const int* in_sizes, int n_in,
                              void* d_out, int out_size)
{
    (void)in_sizes; (void)n_in; (void)out_size;
    const float* x    = (const float*)d_in[0];
    const float* Wa   = (const float*)d_in[1];
    const float* Wx   = (const float*)d_in[2];
    const float* ba   = (const float*)d_in[3];
    const float* bx   = (const float*)d_in[4];
    const float* lmbd = (const float*)d_in[5];
    float* out = (float*)d_out;

    static int smem_set = 0;
    if (!smem_set) {
        cudaFuncSetAttribute(gemm_gates, cudaFuncAttributeMaxDynamicSharedMemorySize, SMEM_TOTAL);
        smem_set = 1;
    }

    convert_f16<<<((size_t)MM * KK / 4) / 256, 256>>>(x, Wa, Wx);   // 16384 blocks
    dim3 grid(DD / BN, MM / BM);   // 8 x 128 = 1024 CTAs
    gemm_gates<<<grid, 256, SMEM_TOTAL>>>(x, ba, bx, lmbd);
    scan_pass2<<<(BB * DD) / 256, 256>>>();
    scan_pass3<<<(BB * SEG * DD) / 256, 256>>>(out);
}